// round 15
// baseline (speedup 1.0000x reference)
#include <cuda_runtime.h>
#include <cuda_bf16.h>
#include <cstdint>

// Problem constants
#define GDIM   64
#define SPAT   (GDIM*GDIM*GDIM)      // 262144 voxels per batch
#define BATCH  2
#define NTOT   (BATCH*SPAT)          // 524288 total voxels
#define NCH    16

// Weights in mma-fragment order (static __device__; referenced ONLY from
// device code — host-side use passes the ATS-readable host shadow => zeros).
// Layout: [mtile][kstep][lane] -> uint4 = {a0,a1,a2,a3} of m16n8k16 A-frag.
__device__ __align__(256) uint4 g_w1f[8 * 4 * 32];   // 16 KB
__device__ __align__(256) uint4 g_w2f[8 * 8 * 32];   // 32 KB
__device__ __align__(256) uint4 g_w3f[8 * 32];       // 4 KB (rows 12..15 zero)

__device__ __forceinline__ uint32_t smem_u32(const void* p) {
    return (uint32_t)__cvta_generic_to_shared(p);
}

#define MMA_BF16(C, A, B0, B1)                                               \
    asm volatile(                                                            \
        "mma.sync.aligned.m16n8k16.row.col.f32.bf16.bf16.f32 "               \
        "{%0,%1,%2,%3},{%4,%5,%6,%7},{%8,%9},{%0,%1,%2,%3};"                 \
        : "+f"((C)[0]), "+f"((C)[1]), "+f"((C)[2]), "+f"((C)[3])             \
        : "r"((A)[0]), "r"((A)[1]), "r"((A)[2]), "r"((A)[3]),                \
          "r"(B0), "r"(B1))

#define LDMX4T(B0, B1, B2, B3, ADDR)                                         \
    asm volatile(                                                            \
        "ldmatrix.sync.aligned.m8n8.x4.trans.shared.b16 {%0,%1,%2,%3},[%4];" \
        : "=r"(B0), "=r"(B1), "=r"(B2), "=r"(B3) : "r"(ADDR))

// Smem layout (dynamic, 52224 B; 3 CTAs/SM):
//   [0     .. 34816)  sH   128 x 136 bf16 — holds H1, then REUSED for H2
//   [34816 .. 52224)  sP   64 x 136 bf16  (gemm1 input; dead after gemm1)
//   [34816 .. 41152)  sD   12 x 132 fp32  (overlays sP, written in gemm3)
#define OFF_P 34816
#define SMEM_BYTES 52224

// ---------------------------------------------------------------------------
// Weight convert fp32 -> bf16 in A-fragment order.
// ---------------------------------------------------------------------------
__device__ __forceinline__ uint32_t pk2(const float* w, int K, int o, int k) {
    __nv_bfloat162 t = __floats2bfloat162_rn(w[o * K + k], w[o * K + k + 1]);
    return *(uint32_t*)&t;
}

__global__ void k_convert(const float* __restrict__ w1,
                          const float* __restrict__ w2,
                          const float* __restrict__ w3) {
    int tid = blockIdx.x * blockDim.x + threadIdx.x;
    int stride = gridDim.x * blockDim.x;
    // w1: 8 mtiles x 4 ksteps x 32 lanes
    for (int i = tid; i < 8 * 4 * 32; i += stride) {
        int mt = i >> 7, ks = (i >> 5) & 3, ln = i & 31;
        int m = mt * 16 + (ln >> 2), k = ks * 16 + (ln & 3) * 2;
        uint4 f;
        f.x = pk2(w1, 64, m, k);
        f.y = pk2(w1, 64, m + 8, k);
        f.z = pk2(w1, 64, m, k + 8);
        f.w = pk2(w1, 64, m + 8, k + 8);
        g_w1f[i] = f;
    }
    // w2: 8 mtiles x 8 ksteps x 32 lanes
    for (int i = tid; i < 8 * 8 * 32; i += stride) {
        int mt = i >> 8, ks = (i >> 5) & 7, ln = i & 31;
        int m = mt * 16 + (ln >> 2), k = ks * 16 + (ln & 3) * 2;
        uint4 f;
        f.x = pk2(w2, 128, m, k);
        f.y = pk2(w2, 128, m + 8, k);
        f.z = pk2(w2, 128, m, k + 8);
        f.w = pk2(w2, 128, m + 8, k + 8);
        g_w2f[i] = f;
    }
    // w3: 1 mtile (16 rows, 12 real) x 8 ksteps x 32 lanes
    for (int i = tid; i < 8 * 32; i += stride) {
        int ks = i >> 5, ln = i & 31;
        int m = ln >> 2, k = ks * 16 + (ln & 3) * 2;
        uint4 f;
        f.x = pk2(w3, 128, m, k);          // m <= 7, always real
        f.y = (m + 8 < 12) ? pk2(w3, 128, m + 8, k) : 0u;
        f.z = pk2(w3, 128, m, k + 8);
        f.w = (m + 8 < 12) ? pk2(w3, 128, m + 8, k + 8) : 0u;
        g_w3f[i] = f;
    }
}

// ---------------------------------------------------------------------------
// Fully fused NCA step. One block = 128 voxels (two consecutive x-rows:
// y0, y0+1 at fixed b,z). 256 threads, 8 warps, warp grid 4(M) x 2(N).
// ---------------------------------------------------------------------------
__global__ void __launch_bounds__(256, 3)
k_fused(const float* __restrict__ state,
        const float* __restrict__ b1,
        const float* __restrict__ b2,
        const float* __restrict__ b3,
        float* __restrict__ out) {
    extern __shared__ __align__(16) char uSmem[];
    __nv_bfloat16* sH = (__nv_bfloat16*)uSmem;                // 128*136 (H1, then H2)
    __nv_bfloat16* sP = (__nv_bfloat16*)(uSmem + OFF_P);      // 64*136
    float*         sD = (float*)(uSmem + OFF_P);              // 12*132

    const int tid  = threadIdx.x;
    const int warp = tid >> 5;
    const int lane = tid & 31;

    const int bid = blockIdx.x;            // 0..4095
    const int b   = bid >> 11;
    const int z   = (bid >> 5) & 63;
    const int y0  = (bid & 31) * 2;

    // ---- perceive stencil: direct LDG + shuffles; 12 shared row-loads
    // produce BOTH y-outputs (y0, y0+1) per (ch, xq) task. ----
    {
        const float WS[9]  = {1, 2, 1, 2, 4, 2, 1, 2, 1};
        const float WDY[9] = {-1, 0, 1, -2, 0, 2, -1, 0, 1};
        const float WDZ[9] = {-1, -2, -1, 0, 0, 0, 1, 2, 1};
        const int xqi = tid & 15;
        const int ch  = (tid >> 4) & 15;
        const int xq  = xqi * 4;
        const float* chbase = state + (((size_t)(b * NCH + ch)) << 18) + xq;

        float S0[6], DY0[6], DZ0[6], S1[6], DY1[6], DZ1[6];
        float id0[4], id1[4];
#pragma unroll
        for (int j = 0; j < 6; ++j) {
            S0[j] = 0.f; DY0[j] = 0.f; DZ0[j] = 0.f;
            S1[j] = 0.f; DY1[j] = 0.f; DZ1[j] = 0.f;
        }

#pragma unroll
        for (int a = 0; a < 3; ++a) {
            int cz = min(max(z + a - 1, 0), 63);
#pragma unroll
            for (int yy = 0; yy < 4; ++yy) {
                int cy = min(max(y0 + yy - 1, 0), 63);
                float4 v4 = *(const float4*)&chbase[(cz << 12) + (cy << 6)];
                float xl = __shfl_up_sync(0xFFFFFFFFu, v4.w, 1);
                float xr = __shfl_down_sync(0xFFFFFFFFu, v4.x, 1);
                if (xqi == 0)  xl = v4.x;   // clamp at x=0
                if (xqi == 15) xr = v4.w;   // clamp at x=63
                float v[6] = {xl, v4.x, v4.y, v4.z, v4.w, xr};
                if (a == 1 && yy == 1) { id0[0]=v[1]; id0[1]=v[2]; id0[2]=v[3]; id0[3]=v[4]; }
                if (a == 1 && yy == 2) { id1[0]=v[1]; id1[1]=v[2]; id1[2]=v[3]; id1[3]=v[4]; }
                if (yy < 3) {           // contributes to y0 output (bb = yy)
                    const int r = a * 3 + yy;
#pragma unroll
                    for (int j = 0; j < 6; ++j) {
                        S0[j] += WS[r] * v[j];
                        if (WDY[r] != 0.f) DY0[j] += WDY[r] * v[j];
                        if (WDZ[r] != 0.f) DZ0[j] += WDZ[r] * v[j];
                    }
                }
                if (yy > 0) {           // contributes to y0+1 output (bb = yy-1)
                    const int r = a * 3 + yy - 1;
#pragma unroll
                    for (int j = 0; j < 6; ++j) {
                        S1[j] += WS[r] * v[j];
                        if (WDY[r] != 0.f) DY1[j] += WDY[r] * v[j];
                        if (WDZ[r] != 0.f) DZ1[j] += WDZ[r] * v[j];
                    }
                }
            }
        }

#pragma unroll
        for (int yi = 0; yi < 2; ++yi) {
            const float* S  = yi ? S1 : S0;
            const float* DY = yi ? DY1 : DY0;
            const float* DZ = yi ? DZ1 : DZ0;
            const float* id = yi ? id1 : id0;
            float ox[4], oy[4], oz[4];
#pragma unroll
            for (int i = 0; i < 4; ++i) {
                ox[i] = (S[i + 2] - S[i]) * (1.f / 16.f);
                oy[i] = (DY[i] + 2.f * DY[i + 1] + DY[i + 2]) * (1.f / 16.f);
                oz[i] = (DZ[i] + 2.f * DZ[i + 1] + DZ[i + 2]) * (1.f / 16.f);
            }
            const int col = yi * 64 + xq;
            __nv_bfloat162* p;
            p = (__nv_bfloat162*)&sP[(0 * 16 + ch) * 136 + col];
            p[0] = __floats2bfloat162_rn(id[0], id[1]);
            p[1] = __floats2bfloat162_rn(id[2], id[3]);
            p = (__nv_bfloat162*)&sP[(1 * 16 + ch) * 136 + col];
            p[0] = __floats2bfloat162_rn(ox[0], ox[1]);
            p[1] = __floats2bfloat162_rn(ox[2], ox[3]);
            p = (__nv_bfloat162*)&sP[(2 * 16 + ch) * 136 + col];
            p[0] = __floats2bfloat162_rn(oy[0], oy[1]);
            p[1] = __floats2bfloat162_rn(oy[2], oy[3]);
            p = (__nv_bfloat162*)&sP[(3 * 16 + ch) * 136 + col];
            p[0] = __floats2bfloat162_rn(oz[0], oz[1]);
            p[1] = __floats2bfloat162_rn(oz[2], oz[3]);
        }
    }
    __syncthreads();

    // warp tiling: 4(M) x 2(N); warp tile = 32 out-rows x 64 voxel-cols
    const int wm   = warp >> 1;
    const int wn   = warp & 1;
    const int mrow = (lane >> 2);          // 0..7
    const int brow = lane & 15;
    const int bch  = (lane >> 4) * 8;

    float acc[2][8][4];

    // ---- gemm1: h1 = relu(W1 @ perc + b1), K=64 ----
#pragma unroll
    for (int mi = 0; mi < 2; ++mi)
#pragma unroll
        for (int nt = 0; nt < 8; ++nt)
#pragma unroll
            for (int i = 0; i < 4; ++i) acc[mi][nt][i] = 0.f;

#pragma unroll
    for (int ks = 0; ks < 4; ++ks) {
        uint4 f0 = g_w1f[((wm * 2 + 0) * 4 + ks) * 32 + lane];
        uint4 f1 = g_w1f[((wm * 2 + 1) * 4 + ks) * 32 + lane];
#pragma unroll
        for (int ntp = 0; ntp < 4; ++ntp) {
            uint32_t addr = smem_u32(&sP[(ks * 16 + brow) * 136 + wn * 64 + ntp * 16 + bch]);
            uint32_t b0r, b1r, b2r, b3r;
            LDMX4T(b0r, b1r, b2r, b3r, addr);
            MMA_BF16(acc[0][2 * ntp],     (uint32_t*)&f0, b0r, b1r);
            MMA_BF16(acc[0][2 * ntp + 1], (uint32_t*)&f0, b2r, b3r);
            MMA_BF16(acc[1][2 * ntp],     (uint32_t*)&f1, b0r, b1r);
            MMA_BF16(acc[1][2 * ntp + 1], (uint32_t*)&f1, b2r, b3r);
        }
    }
    // H1 store goes to sH (distinct from sP) — no barrier needed before store
#pragma unroll
    for (int mi = 0; mi < 2; ++mi) {
        const int rm = wm * 32 + mi * 16 + mrow;
        const float bm  = b1[rm];
        const float bm8 = b1[rm + 8];
#pragma unroll
        for (int nt = 0; nt < 8; ++nt) {
            int col = wn * 64 + nt * 8 + (lane & 3) * 2;
            *(__nv_bfloat162*)&sH[rm * 136 + col] = __floats2bfloat162_rn(
                fmaxf(acc[mi][nt][0] + bm, 0.f), fmaxf(acc[mi][nt][1] + bm, 0.f));
            *(__nv_bfloat162*)&sH[(rm + 8) * 136 + col] = __floats2bfloat162_rn(
                fmaxf(acc[mi][nt][2] + bm8, 0.f), fmaxf(acc[mi][nt][3] + bm8, 0.f));
        }
    }
    __syncthreads();

    // ---- gemm2: h2 = relu(W2 @ h1 + b2), K=128 ----
#pragma unroll
    for (int mi = 0; mi < 2; ++mi)
#pragma unroll
        for (int nt = 0; nt < 8; ++nt)
#pragma unroll
            for (int i = 0; i < 4; ++i) acc[mi][nt][i] = 0.f;

#pragma unroll
    for (int ks = 0; ks < 8; ++ks) {
        uint4 f0 = g_w2f[((wm * 2 + 0) * 8 + ks) * 32 + lane];
        uint4 f1 = g_w2f[((wm * 2 + 1) * 8 + ks) * 32 + lane];
#pragma unroll
        for (int ntp = 0; ntp < 4; ++ntp) {
            uint32_t addr = smem_u32(&sH[(ks * 16 + brow) * 136 + wn * 64 + ntp * 16 + bch]);
            uint32_t b0r, b1r, b2r, b3r;
            LDMX4T(b0r, b1r, b2r, b3r, addr);
            MMA_BF16(acc[0][2 * ntp],     (uint32_t*)&f0, b0r, b1r);
            MMA_BF16(acc[0][2 * ntp + 1], (uint32_t*)&f0, b2r, b3r);
            MMA_BF16(acc[1][2 * ntp],     (uint32_t*)&f1, b0r, b1r);
            MMA_BF16(acc[1][2 * ntp + 1], (uint32_t*)&f1, b2r, b3r);
        }
    }
    // All warps must finish READING H1 before H2 overwrites the same buffer.
    __syncthreads();
#pragma unroll
    for (int mi = 0; mi < 2; ++mi) {
        const int rm = wm * 32 + mi * 16 + mrow;
        const float bm  = b2[rm];
        const float bm8 = b2[rm + 8];
#pragma unroll
        for (int nt = 0; nt < 8; ++nt) {
            int col = wn * 64 + nt * 8 + (lane & 3) * 2;
            *(__nv_bfloat162*)&sH[rm * 136 + col] = __floats2bfloat162_rn(
                fmaxf(acc[mi][nt][0] + bm, 0.f), fmaxf(acc[mi][nt][1] + bm, 0.f));
            *(__nv_bfloat162*)&sH[(rm + 8) * 136 + col] = __floats2bfloat162_rn(
                fmaxf(acc[mi][nt][2] + bm8, 0.f), fmaxf(acc[mi][nt][3] + bm8, 0.f));
        }
    }
    __syncthreads();

    // ---- gemm3: delta = W3 @ h2 (all 8 warps; warp w -> cols w*16..+15) ----
    {
        const int w3m = lane >> 2;
        float acc3[2][4];
#pragma unroll
        for (int nt = 0; nt < 2; ++nt)
#pragma unroll
            for (int i = 0; i < 4; ++i) acc3[nt][i] = 0.f;

#pragma unroll
        for (int ks = 0; ks < 8; ++ks) {
            uint4 f0 = g_w3f[ks * 32 + lane];
            uint32_t addr = smem_u32(&sH[(ks * 16 + brow) * 136 + warp * 16 + bch]);
            uint32_t b0r, b1r, b2r, b3r;
            LDMX4T(b0r, b1r, b2r, b3r, addr);
            MMA_BF16(acc3[0], (uint32_t*)&f0, b0r, b1r);
            MMA_BF16(acc3[1], (uint32_t*)&f0, b2r, b3r);
        }
#pragma unroll
        for (int nt = 0; nt < 2; ++nt) {
            int col = warp * 16 + nt * 8 + (lane & 3) * 2;
            sD[w3m * 132 + col]     = acc3[nt][0];
            sD[w3m * 132 + col + 1] = acc3[nt][1];
            if (w3m + 8 < 12) {
                sD[(w3m + 8) * 132 + col]     = acc3[nt][2];
                sD[(w3m + 8) * 132 + col + 1] = acc3[nt][3];
            }
        }
    }
    __syncthreads();

    // ---- NCA epilogue: 128 voxels x 16 ch, 8 channels per thread ----
    {
        const int v   = tid & 127;
        const int grp = tid >> 7;          // 0: ch0-7, 1: ch8-15
        const int s   = (z << 12) + (y0 << 6) + v;

        const float* st = state + (size_t)b * NCH * SPAT;
        float* ot = out + (size_t)b * NCH * SPAT;

        if (grp == 0) {
            float e    = st[s];
            float anch = st[SPAT + s];
            float pos = (z >= 3) ? 1.f : anch;
            float legal = fminf(fmaxf((1.f - e) * pos, 0.f), 1.f);

            ot[0 * SPAT + s] = e;
            ot[1 * SPAT + s] = anch;
            ot[2 * SPAT + s] = st[2 * SPAT + s];
            ot[3 * SPAT + s] = st[3 * SPAT + s];
#pragma unroll
            for (int j = 0; j < 4; ++j) {
                float d = sD[j * 132 + v] + b3[j];
                float g = fminf(fmaxf(st[(4 + j) * SPAT + s] + 0.1f * d, 0.f), 1.f);
                if (j == 0) g = g * (1.f - e) * legal;
                ot[(4 + j) * SPAT + s] = g;
            }
        } else {
#pragma unroll
            for (int j = 4; j < 12; ++j) {
                float d = sD[j * 132 + v] + b3[j];
                float g = fminf(fmaxf(st[(4 + j) * SPAT + s] + 0.1f * d, 0.f), 1.f);
                ot[(4 + j) * SPAT + s] = g;
            }
        }
    }
}

// ---------------------------------------------------------------------------
extern "C" void kernel_launch(void* const* d_in, const int* in_sizes, int n_in,
                              void* d_out, int out_size) {
    const float* state = (const float*)d_in[0];
    const float* w1 = (const float*)d_in[1];
    const float* b1 = (const float*)d_in[2];
    const float* w2 = (const float*)d_in[3];
    const float* b2 = (const float*)d_in[4];
    const float* w3 = (const float*)d_in[5];
    const float* b3 = (const float*)d_in[6];
    float* out = (float*)d_out;

    cudaFuncSetAttribute(k_fused, cudaFuncAttributeMaxDynamicSharedMemorySize,
                         SMEM_BYTES);

    // 1) weights fp32 -> bf16 in fragment order
    k_convert<<<24, 256>>>(w1, w2, w3);

    // 2) fused perceive + MLP + epilogue (one block per 128 voxels)
    k_fused<<<NTOT / 128, 256, SMEM_BYTES>>>(state, b1, b2, b3, out);
}

// round 16
// speedup vs baseline: 1.0506x; 1.0506x over previous
#include <cuda_runtime.h>
#include <cuda_bf16.h>
#include <cstdint>

// Problem constants
#define GDIM   64
#define SPAT   (GDIM*GDIM*GDIM)      // 262144 voxels per batch
#define BATCH  2
#define NTOT   (BATCH*SPAT)          // 524288 total voxels
#define NCH    16

// Weights in mma-fragment order (static __device__; referenced ONLY from
// device code — host-side use passes the ATS-readable host shadow => zeros).
// Layout: [mtile][kstep][lane] -> uint4 = {a0,a1,a2,a3} of m16n8k16 A-frag.
__device__ __align__(256) uint4 g_w1f[8 * 4 * 32];   // 16 KB
__device__ __align__(256) uint4 g_w2f[8 * 8 * 32];   // 32 KB
__device__ __align__(256) uint4 g_w3f[8 * 32];       // 4 KB (rows 12..15 zero)

__device__ __forceinline__ uint32_t smem_u32(const void* p) {
    return (uint32_t)__cvta_generic_to_shared(p);
}

#define MMA_BF16(C, A, B0, B1)                                               \
    asm volatile(                                                            \
        "mma.sync.aligned.m16n8k16.row.col.f32.bf16.bf16.f32 "               \
        "{%0,%1,%2,%3},{%4,%5,%6,%7},{%8,%9},{%0,%1,%2,%3};"                 \
        : "+f"((C)[0]), "+f"((C)[1]), "+f"((C)[2]), "+f"((C)[3])             \
        : "r"((A)[0]), "r"((A)[1]), "r"((A)[2]), "r"((A)[3]),                \
          "r"(B0), "r"(B1))

#define LDMX4T(B0, B1, B2, B3, ADDR)                                         \
    asm volatile(                                                            \
        "ldmatrix.sync.aligned.m8n8.x4.trans.shared.b16 {%0,%1,%2,%3},[%4];" \
        : "=r"(B0), "=r"(B1), "=r"(B2), "=r"(B3) : "r"(ADDR))

// Smem layout (dynamic, 87040 B; 2 CTAs/SM):
//   [0      .. 34816)  sH1  128 x 136 bf16
//   [34816  .. 69632)  sH2  128 x 136 bf16
//   [69632  .. 87040)  sP   64 x 136 bf16   (gemm1 input; dead after gemm1)
//   [69632  .. 76000)  sD   12 x 132 fp32   (overlays sP, written in gemm3)
#define SMEM_BYTES 87040

// ---------------------------------------------------------------------------
// Weight convert fp32 -> bf16 in A-fragment order.
// ---------------------------------------------------------------------------
__device__ __forceinline__ uint32_t pk2(const float* w, int K, int o, int k) {
    __nv_bfloat162 t = __floats2bfloat162_rn(w[o * K + k], w[o * K + k + 1]);
    return *(uint32_t*)&t;
}

__global__ void k_convert(const float* __restrict__ w1,
                          const float* __restrict__ w2,
                          const float* __restrict__ w3) {
    int tid = blockIdx.x * blockDim.x + threadIdx.x;
    int stride = gridDim.x * blockDim.x;
    // w1: 8 mtiles x 4 ksteps x 32 lanes
    for (int i = tid; i < 8 * 4 * 32; i += stride) {
        int mt = i >> 7, ks = (i >> 5) & 3, ln = i & 31;
        int m = mt * 16 + (ln >> 2), k = ks * 16 + (ln & 3) * 2;
        uint4 f;
        f.x = pk2(w1, 64, m, k);
        f.y = pk2(w1, 64, m + 8, k);
        f.z = pk2(w1, 64, m, k + 8);
        f.w = pk2(w1, 64, m + 8, k + 8);
        g_w1f[i] = f;
    }
    // w2: 8 mtiles x 8 ksteps x 32 lanes
    for (int i = tid; i < 8 * 8 * 32; i += stride) {
        int mt = i >> 8, ks = (i >> 5) & 7, ln = i & 31;
        int m = mt * 16 + (ln >> 2), k = ks * 16 + (ln & 3) * 2;
        uint4 f;
        f.x = pk2(w2, 128, m, k);
        f.y = pk2(w2, 128, m + 8, k);
        f.z = pk2(w2, 128, m, k + 8);
        f.w = pk2(w2, 128, m + 8, k + 8);
        g_w2f[i] = f;
    }
    // w3: 1 mtile (16 rows, 12 real) x 8 ksteps x 32 lanes
    for (int i = tid; i < 8 * 32; i += stride) {
        int ks = i >> 5, ln = i & 31;
        int m = ln >> 2, k = ks * 16 + (ln & 3) * 2;
        uint4 f;
        f.x = pk2(w3, 128, m, k);          // m <= 7, always real
        f.y = (m + 8 < 12) ? pk2(w3, 128, m + 8, k) : 0u;
        f.z = pk2(w3, 128, m, k + 8);
        f.w = (m + 8 < 12) ? pk2(w3, 128, m + 8, k + 8) : 0u;
        g_w3f[i] = f;
    }
}

// ---------------------------------------------------------------------------
// Fully fused NCA step. One block = 128 voxels (two consecutive x-rows:
// y0, y0+1 at fixed b,z). 256 threads, 8 warps.
// GEMM warp tiling: N-partitioned — warp w owns ALL 128 out-rows x 16 voxel
// cols [w*16, w*16+16). Each B-tile is ldmatrix'd exactly once per block;
// weight A-fragments stream through cheap coalesced LDG (L1-cached).
// ---------------------------------------------------------------------------
__global__ void __launch_bounds__(256, 2)
k_fused(const float* __restrict__ state,
        const float* __restrict__ b1,
        const float* __restrict__ b2,
        const float* __restrict__ b3,
        float* __restrict__ out) {
    extern __shared__ __align__(16) char uSmem[];
    __nv_bfloat16* sH1 = (__nv_bfloat16*)uSmem;               // 128*136
    __nv_bfloat16* sH2 = (__nv_bfloat16*)(uSmem + 34816);     // 128*136
    __nv_bfloat16* sP  = (__nv_bfloat16*)(uSmem + 69632);     // 64*136
    float*         sD  = (float*)(uSmem + 69632);             // 12*132

    const int tid  = threadIdx.x;
    const int warp = tid >> 5;
    const int lane = tid & 31;

    const int bid = blockIdx.x;            // 0..4095
    const int b   = bid >> 11;
    const int z   = (bid >> 5) & 63;
    const int y0  = (bid & 31) * 2;

    // ---- perceive stencil: direct LDG + warp shuffles (R10 verbatim) ----
    {
        const float WS[9]  = {1, 2, 1, 2, 4, 2, 1, 2, 1};
        const float WDY[9] = {-1, 0, 1, -2, 0, 2, -1, 0, 1};
        const float WDZ[9] = {-1, -2, -1, 0, 0, 0, 1, 2, 1};
        const int xqi = tid & 15;
        const int ch  = (tid >> 4) & 15;
        const int xq  = xqi * 4;
        const float* chbase = state + (((size_t)(b * NCH + ch)) << 18) + xq;

#pragma unroll
        for (int t = 0; t < 2; ++t) {
            const int yi = t;
            const int y  = y0 + yi;

            float S[6], DY[6], DZ[6], id4[4];
#pragma unroll
            for (int j = 0; j < 6; ++j) { S[j] = 0.f; DY[j] = 0.f; DZ[j] = 0.f; }

#pragma unroll
            for (int a = 0; a < 3; ++a) {
                int cz = min(max(z + a - 1, 0), 63);
#pragma unroll
                for (int bb = 0; bb < 3; ++bb) {
                    int cy = min(max(y + bb - 1, 0), 63);
                    int r = a * 3 + bb;
                    float4 v4 = *(const float4*)&chbase[(cz << 12) + (cy << 6)];
                    float xl = __shfl_up_sync(0xFFFFFFFFu, v4.w, 1);
                    float xr = __shfl_down_sync(0xFFFFFFFFu, v4.x, 1);
                    if (xqi == 0)  xl = v4.x;   // clamp at x=0
                    if (xqi == 15) xr = v4.w;   // clamp at x=63
                    float v[6] = {xl, v4.x, v4.y, v4.z, v4.w, xr};
                    if (r == 4) { id4[0] = v[1]; id4[1] = v[2]; id4[2] = v[3]; id4[3] = v[4]; }
#pragma unroll
                    for (int j = 0; j < 6; ++j) {
                        S[j] += WS[r] * v[j];
                        if (WDY[r] != 0.f) DY[j] += WDY[r] * v[j];
                        if (WDZ[r] != 0.f) DZ[j] += WDZ[r] * v[j];
                    }
                }
            }

            float ox[4], oy[4], oz[4];
#pragma unroll
            for (int i = 0; i < 4; ++i) {
                ox[i] = (S[i + 2] - S[i]) * (1.f / 16.f);
                oy[i] = (DY[i] + 2.f * DY[i + 1] + DY[i + 2]) * (1.f / 16.f);
                oz[i] = (DZ[i] + 2.f * DZ[i + 1] + DZ[i + 2]) * (1.f / 16.f);
            }
            const int col = yi * 64 + xq;
            __nv_bfloat162* p;
            p = (__nv_bfloat162*)&sP[(0 * 16 + ch) * 136 + col];
            p[0] = __floats2bfloat162_rn(id4[0], id4[1]);
            p[1] = __floats2bfloat162_rn(id4[2], id4[3]);
            p = (__nv_bfloat162*)&sP[(1 * 16 + ch) * 136 + col];
            p[0] = __floats2bfloat162_rn(ox[0], ox[1]);
            p[1] = __floats2bfloat162_rn(ox[2], ox[3]);
            p = (__nv_bfloat162*)&sP[(2 * 16 + ch) * 136 + col];
            p[0] = __floats2bfloat162_rn(oy[0], oy[1]);
            p[1] = __floats2bfloat162_rn(oy[2], oy[3]);
            p = (__nv_bfloat162*)&sP[(3 * 16 + ch) * 136 + col];
            p[0] = __floats2bfloat162_rn(oz[0], oz[1]);
            p[1] = __floats2bfloat162_rn(oz[2], oz[3]);
        }
    }
    __syncthreads();

    const int mrow = (lane >> 2);          // 0..7
    const int brow = lane & 15;
    const int bch  = (lane >> 4) * 8;
    const int ncol0 = warp * 16 + (lane & 3) * 2;   // epilogue col base

    float acc[8][2][4];                    // [mtile][ntile][reg]: 64 regs

    // ---- gemm1: h1 = relu(W1 @ perc + b1), K=64 ----
#pragma unroll
    for (int mt = 0; mt < 8; ++mt)
#pragma unroll
        for (int nt = 0; nt < 2; ++nt)
#pragma unroll
            for (int i = 0; i < 4; ++i) acc[mt][nt][i] = 0.f;

#pragma unroll
    for (int ks = 0; ks < 4; ++ks) {
        uint32_t addr = smem_u32(&sP[(ks * 16 + brow) * 136 + warp * 16 + bch]);
        uint32_t b0r, b1r, b2r, b3r;
        LDMX4T(b0r, b1r, b2r, b3r, addr);
#pragma unroll
        for (int mt = 0; mt < 8; ++mt) {
            uint4 f = g_w1f[(mt * 4 + ks) * 32 + lane];
            MMA_BF16(acc[mt][0], (uint32_t*)&f, b0r, b1r);
            MMA_BF16(acc[mt][1], (uint32_t*)&f, b2r, b3r);
        }
    }
#pragma unroll
    for (int mt = 0; mt < 8; ++mt) {
        const int rm = mt * 16 + mrow;
        const float bm  = b1[rm];
        const float bm8 = b1[rm + 8];
#pragma unroll
        for (int nt = 0; nt < 2; ++nt) {
            int col = ncol0 + nt * 8;
            *(__nv_bfloat162*)&sH1[rm * 136 + col] = __floats2bfloat162_rn(
                fmaxf(acc[mt][nt][0] + bm, 0.f), fmaxf(acc[mt][nt][1] + bm, 0.f));
            *(__nv_bfloat162*)&sH1[(rm + 8) * 136 + col] = __floats2bfloat162_rn(
                fmaxf(acc[mt][nt][2] + bm8, 0.f), fmaxf(acc[mt][nt][3] + bm8, 0.f));
        }
    }
    __syncthreads();

    // ---- gemm2: h2 = relu(W2 @ h1 + b2), K=128 ----
#pragma unroll
    for (int mt = 0; mt < 8; ++mt)
#pragma unroll
        for (int nt = 0; nt < 2; ++nt)
#pragma unroll
            for (int i = 0; i < 4; ++i) acc[mt][nt][i] = 0.f;

#pragma unroll
    for (int ks = 0; ks < 8; ++ks) {
        uint32_t addr = smem_u32(&sH1[(ks * 16 + brow) * 136 + warp * 16 + bch]);
        uint32_t b0r, b1r, b2r, b3r;
        LDMX4T(b0r, b1r, b2r, b3r, addr);
#pragma unroll
        for (int mt = 0; mt < 8; ++mt) {
            uint4 f = g_w2f[(mt * 8 + ks) * 32 + lane];
            MMA_BF16(acc[mt][0], (uint32_t*)&f, b0r, b1r);
            MMA_BF16(acc[mt][1], (uint32_t*)&f, b2r, b3r);
        }
    }
#pragma unroll
    for (int mt = 0; mt < 8; ++mt) {
        const int rm = mt * 16 + mrow;
        const float bm  = b2[rm];
        const float bm8 = b2[rm + 8];
#pragma unroll
        for (int nt = 0; nt < 2; ++nt) {
            int col = ncol0 + nt * 8;
            *(__nv_bfloat162*)&sH2[rm * 136 + col] = __floats2bfloat162_rn(
                fmaxf(acc[mt][nt][0] + bm, 0.f), fmaxf(acc[mt][nt][1] + bm, 0.f));
            *(__nv_bfloat162*)&sH2[(rm + 8) * 136 + col] = __floats2bfloat162_rn(
                fmaxf(acc[mt][nt][2] + bm8, 0.f), fmaxf(acc[mt][nt][3] + bm8, 0.f));
        }
    }
    __syncthreads();

    // ---- gemm3: delta = W3 @ h2 (warp w -> cols w*16..+15; R10 verbatim) ----
    {
        const int w3m = lane >> 2;
        float acc3[2][4];
#pragma unroll
        for (int nt = 0; nt < 2; ++nt)
#pragma unroll
            for (int i = 0; i < 4; ++i) acc3[nt][i] = 0.f;

#pragma unroll
        for (int ks = 0; ks < 8; ++ks) {
            uint4 f0 = g_w3f[ks * 32 + lane];
            uint32_t addr = smem_u32(&sH2[(ks * 16 + brow) * 136 + warp * 16 + bch]);
            uint32_t b0r, b1r, b2r, b3r;
            LDMX4T(b0r, b1r, b2r, b3r, addr);
            MMA_BF16(acc3[0], (uint32_t*)&f0, b0r, b1r);
            MMA_BF16(acc3[1], (uint32_t*)&f0, b2r, b3r);
        }
#pragma unroll
        for (int nt = 0; nt < 2; ++nt) {
            int col = warp * 16 + nt * 8 + (lane & 3) * 2;
            sD[w3m * 132 + col]     = acc3[nt][0];
            sD[w3m * 132 + col + 1] = acc3[nt][1];
            if (w3m + 8 < 12) {
                sD[(w3m + 8) * 132 + col]     = acc3[nt][2];
                sD[(w3m + 8) * 132 + col + 1] = acc3[nt][3];
            }
        }
    }
    __syncthreads();

    // ---- NCA epilogue: 128 voxels x 16 ch, 8 channels per thread ----
    {
        const int v   = tid & 127;
        const int grp = tid >> 7;          // 0: ch0-7, 1: ch8-15
        const int s   = (z << 12) + (y0 << 6) + v;

        const float* st = state + (size_t)b * NCH * SPAT;
        float* ot = out + (size_t)b * NCH * SPAT;

        if (grp == 0) {
            float e    = st[s];
            float anch = st[SPAT + s];
            float pos = (z >= 3) ? 1.f : anch;
            float legal = fminf(fmaxf((1.f - e) * pos, 0.f), 1.f);

            ot[0 * SPAT + s] = e;
            ot[1 * SPAT + s] = anch;
            ot[2 * SPAT + s] = st[2 * SPAT + s];
            ot[3 * SPAT + s] = st[3 * SPAT + s];
#pragma unroll
            for (int j = 0; j < 4; ++j) {
                float d = sD[j * 132 + v] + b3[j];
                float g = fminf(fmaxf(st[(4 + j) * SPAT + s] + 0.1f * d, 0.f), 1.f);
                if (j == 0) g = g * (1.f - e) * legal;
                ot[(4 + j) * SPAT + s] = g;
            }
        } else {
#pragma unroll
            for (int j = 4; j < 12; ++j) {
                float d = sD[j * 132 + v] + b3[j];
                float g = fminf(fmaxf(st[(4 + j) * SPAT + s] + 0.1f * d, 0.f), 1.f);
                ot[(4 + j) * SPAT + s] = g;
            }
        }
    }
}

// ---------------------------------------------------------------------------
extern "C" void kernel_launch(void* const* d_in, const int* in_sizes, int n_in,
                              void* d_out, int out_size) {
    const float* state = (const float*)d_in[0];
    const float* w1 = (const float*)d_in[1];
    const float* b1 = (const float*)d_in[2];
    const float* w2 = (const float*)d_in[3];
    const float* b2 = (const float*)d_in[4];
    const float* w3 = (const float*)d_in[5];
    const float* b3 = (const float*)d_in[6];
    float* out = (float*)d_out;

    cudaFuncSetAttribute(k_fused, cudaFuncAttributeMaxDynamicSharedMemorySize,
                         SMEM_BYTES);

    // 1) weights fp32 -> bf16 in fragment order
    k_convert<<<24, 256>>>(w1, w2, w3);

    // 2) fused perceive + MLP + epilogue (one block per 128 voxels)
    k_fused<<<NTOT / 128, 256, SMEM_BYTES>>>(state, b1, b2, b3, out);
}

// round 17
// speedup vs baseline: 1.2314x; 1.1721x over previous
#include <cuda_runtime.h>
#include <cuda_bf16.h>
#include <cstdint>

// Problem constants
#define GDIM   64
#define SPAT   (GDIM*GDIM*GDIM)      // 262144 voxels per batch
#define BATCH  2
#define NTOT   (BATCH*SPAT)          // 524288 total voxels
#define NCH    16

// Weights in mma-fragment order (static __device__; referenced ONLY from
// device code — host-side use passes the ATS-readable host shadow => zeros).
// Layout: [mtile][kstep][lane] -> uint4 = {a0,a1,a2,a3} of m16n8k16 A-frag.
__device__ __align__(256) uint4 g_w1f[8 * 4 * 32];   // 16 KB
__device__ __align__(256) uint4 g_w2f[8 * 8 * 32];   // 32 KB
__device__ __align__(256) uint4 g_w3f[8 * 32];       // 4 KB (rows 12..15 zero)

__device__ __forceinline__ uint32_t smem_u32(const void* p) {
    return (uint32_t)__cvta_generic_to_shared(p);
}

#define MMA_BF16(C, A, B0, B1)                                               \
    asm volatile(                                                            \
        "mma.sync.aligned.m16n8k16.row.col.f32.bf16.bf16.f32 "               \
        "{%0,%1,%2,%3},{%4,%5,%6,%7},{%8,%9},{%0,%1,%2,%3};"                 \
        : "+f"((C)[0]), "+f"((C)[1]), "+f"((C)[2]), "+f"((C)[3])             \
        : "r"((A)[0]), "r"((A)[1]), "r"((A)[2]), "r"((A)[3]),                \
          "r"(B0), "r"(B1))

#define LDMX4T(B0, B1, B2, B3, ADDR)                                         \
    asm volatile(                                                            \
        "ldmatrix.sync.aligned.m8n8.x4.trans.shared.b16 {%0,%1,%2,%3},[%4];" \
        : "=r"(B0), "=r"(B1), "=r"(B2), "=r"(B3) : "r"(ADDR))

// Smem layout (dynamic, 87040 B; 2 CTAs/SM):
//   [0      .. 34816)  sH1  128 x 136 bf16
//   [34816  .. 69632)  sH2  128 x 136 bf16
//   [69632  .. 87040)  sP   64 x 136 bf16   (gemm1 input; dead after gemm1)
//   [69632  .. 76000)  sD   12 x 132 fp32   (overlays sP, written in gemm3)
#define SMEM_BYTES 87040

// ---------------------------------------------------------------------------
// Weight convert fp32 -> bf16 in A-fragment order.
// ---------------------------------------------------------------------------
__device__ __forceinline__ uint32_t pk2(const float* w, int K, int o, int k) {
    __nv_bfloat162 t = __floats2bfloat162_rn(w[o * K + k], w[o * K + k + 1]);
    return *(uint32_t*)&t;
}

__global__ void k_convert(const float* __restrict__ w1,
                          const float* __restrict__ w2,
                          const float* __restrict__ w3) {
    int tid = blockIdx.x * blockDim.x + threadIdx.x;
    int stride = gridDim.x * blockDim.x;
    // w1: 8 mtiles x 4 ksteps x 32 lanes
    for (int i = tid; i < 8 * 4 * 32; i += stride) {
        int mt = i >> 7, ks = (i >> 5) & 3, ln = i & 31;
        int m = mt * 16 + (ln >> 2), k = ks * 16 + (ln & 3) * 2;
        uint4 f;
        f.x = pk2(w1, 64, m, k);
        f.y = pk2(w1, 64, m + 8, k);
        f.z = pk2(w1, 64, m, k + 8);
        f.w = pk2(w1, 64, m + 8, k + 8);
        g_w1f[i] = f;
    }
    // w2: 8 mtiles x 8 ksteps x 32 lanes
    for (int i = tid; i < 8 * 8 * 32; i += stride) {
        int mt = i >> 8, ks = (i >> 5) & 7, ln = i & 31;
        int m = mt * 16 + (ln >> 2), k = ks * 16 + (ln & 3) * 2;
        uint4 f;
        f.x = pk2(w2, 128, m, k);
        f.y = pk2(w2, 128, m + 8, k);
        f.z = pk2(w2, 128, m, k + 8);
        f.w = pk2(w2, 128, m + 8, k + 8);
        g_w2f[i] = f;
    }
    // w3: 1 mtile (16 rows, 12 real) x 8 ksteps x 32 lanes
    for (int i = tid; i < 8 * 32; i += stride) {
        int ks = i >> 5, ln = i & 31;
        int m = ln >> 2, k = ks * 16 + (ln & 3) * 2;
        uint4 f;
        f.x = pk2(w3, 128, m, k);          // m <= 7, always real
        f.y = (m + 8 < 12) ? pk2(w3, 128, m + 8, k) : 0u;
        f.z = pk2(w3, 128, m, k + 8);
        f.w = (m + 8 < 12) ? pk2(w3, 128, m + 8, k + 8) : 0u;
        g_w3f[i] = f;
    }
}

// ---------------------------------------------------------------------------
// Fully fused NCA step. One block = 128 voxels (two consecutive x-rows:
// y0, y0+1 at fixed b,z). 256 threads, 8 warps, warp grid 4(M) x 2(N).
// ---------------------------------------------------------------------------
__global__ void __launch_bounds__(256, 2)
k_fused(const float* __restrict__ state,
        const float* __restrict__ b1,
        const float* __restrict__ b2,
        const float* __restrict__ b3,
        float* __restrict__ out) {
    extern __shared__ __align__(16) char uSmem[];
    __nv_bfloat16* sH1 = (__nv_bfloat16*)uSmem;               // 128*136
    __nv_bfloat16* sH2 = (__nv_bfloat16*)(uSmem + 34816);     // 128*136
    __nv_bfloat16* sP  = (__nv_bfloat16*)(uSmem + 69632);     // 64*136
    float*         sD  = (float*)(uSmem + 69632);             // 12*132

    const int tid  = threadIdx.x;
    const int warp = tid >> 5;
    const int lane = tid & 31;

    const int bid = blockIdx.x;            // 0..4095
    const int b   = bid >> 11;
    const int z   = (bid >> 5) & 63;
    const int y0  = (bid & 31) * 2;

    // ---- perceive stencil: 12 distinct rows loaded ONCE into registers,
    //      both y-outputs computed from them (same ALU structure as R10). ----
    {
        const float WS[9]  = {1, 2, 1, 2, 4, 2, 1, 2, 1};
        const float WDY[9] = {-1, 0, 1, -2, 0, 2, -1, 0, 1};
        const float WDZ[9] = {-1, -2, -1, 0, 0, 0, 1, 2, 1};
        const int xqi = tid & 15;
        const int ch  = (tid >> 4) & 15;
        const int xq  = xqi * 4;
        const float* chbase = state + (((size_t)(b * NCH + ch)) << 18) + xq;

        // Front-batched independent loads: 3(z) x 4(y) clamped rows.
        float4 vrow[12];
#pragma unroll
        for (int a = 0; a < 3; ++a) {
            int cz = min(max(z + a - 1, 0), 63);
#pragma unroll
            for (int yy = 0; yy < 4; ++yy) {
                int cy = min(max(y0 + yy - 1, 0), 63);
                vrow[a * 4 + yy] = *(const float4*)&chbase[(cz << 12) + (cy << 6)];
            }
        }

#pragma unroll
        for (int yi = 0; yi < 2; ++yi) {
            float S[6], DY[6], DZ[6], id4[4];
#pragma unroll
            for (int j = 0; j < 6; ++j) { S[j] = 0.f; DY[j] = 0.f; DZ[j] = 0.f; }

#pragma unroll
            for (int a = 0; a < 3; ++a) {
#pragma unroll
                for (int bb = 0; bb < 3; ++bb) {
                    const int r = a * 3 + bb;
                    float4 v4 = vrow[a * 4 + bb + yi];
                    float xl = __shfl_up_sync(0xFFFFFFFFu, v4.w, 1);
                    float xr = __shfl_down_sync(0xFFFFFFFFu, v4.x, 1);
                    if (xqi == 0)  xl = v4.x;   // clamp at x=0
                    if (xqi == 15) xr = v4.w;   // clamp at x=63
                    float v[6] = {xl, v4.x, v4.y, v4.z, v4.w, xr};
                    if (r == 4) { id4[0] = v[1]; id4[1] = v[2]; id4[2] = v[3]; id4[3] = v[4]; }
#pragma unroll
                    for (int j = 0; j < 6; ++j) {
                        S[j] += WS[r] * v[j];
                        if (WDY[r] != 0.f) DY[j] += WDY[r] * v[j];
                        if (WDZ[r] != 0.f) DZ[j] += WDZ[r] * v[j];
                    }
                }
            }

            float ox[4], oy[4], oz[4];
#pragma unroll
            for (int i = 0; i < 4; ++i) {
                ox[i] = (S[i + 2] - S[i]) * (1.f / 16.f);
                oy[i] = (DY[i] + 2.f * DY[i + 1] + DY[i + 2]) * (1.f / 16.f);
                oz[i] = (DZ[i] + 2.f * DZ[i + 1] + DZ[i + 2]) * (1.f / 16.f);
            }
            const int col = yi * 64 + xq;
            __nv_bfloat162* p;
            p = (__nv_bfloat162*)&sP[(0 * 16 + ch) * 136 + col];
            p[0] = __floats2bfloat162_rn(id4[0], id4[1]);
            p[1] = __floats2bfloat162_rn(id4[2], id4[3]);
            p = (__nv_bfloat162*)&sP[(1 * 16 + ch) * 136 + col];
            p[0] = __floats2bfloat162_rn(ox[0], ox[1]);
            p[1] = __floats2bfloat162_rn(ox[2], ox[3]);
            p = (__nv_bfloat162*)&sP[(2 * 16 + ch) * 136 + col];
            p[0] = __floats2bfloat162_rn(oy[0], oy[1]);
            p[1] = __floats2bfloat162_rn(oy[2], oy[3]);
            p = (__nv_bfloat162*)&sP[(3 * 16 + ch) * 136 + col];
            p[0] = __floats2bfloat162_rn(oz[0], oz[1]);
            p[1] = __floats2bfloat162_rn(oz[2], oz[3]);
        }
    }
    __syncthreads();

    // warp tiling: 4(M) x 2(N); warp tile = 32 out-rows x 64 voxel-cols
    const int wm   = warp >> 1;
    const int wn   = warp & 1;
    const int mrow = (lane >> 2);          // 0..7
    const int brow = lane & 15;
    const int bch  = (lane >> 4) * 8;

    float acc[2][8][4];

    // ---- gemm1: h1 = relu(W1 @ perc + b1), K=64 ----
#pragma unroll
    for (int mi = 0; mi < 2; ++mi)
#pragma unroll
        for (int nt = 0; nt < 8; ++nt)
#pragma unroll
            for (int i = 0; i < 4; ++i) acc[mi][nt][i] = 0.f;

#pragma unroll
    for (int ks = 0; ks < 4; ++ks) {
        uint4 f0 = g_w1f[((wm * 2 + 0) * 4 + ks) * 32 + lane];
        uint4 f1 = g_w1f[((wm * 2 + 1) * 4 + ks) * 32 + lane];
#pragma unroll
        for (int ntp = 0; ntp < 4; ++ntp) {
            uint32_t addr = smem_u32(&sP[(ks * 16 + brow) * 136 + wn * 64 + ntp * 16 + bch]);
            uint32_t b0r, b1r, b2r, b3r;
            LDMX4T(b0r, b1r, b2r, b3r, addr);
            MMA_BF16(acc[0][2 * ntp],     (uint32_t*)&f0, b0r, b1r);
            MMA_BF16(acc[0][2 * ntp + 1], (uint32_t*)&f0, b2r, b3r);
            MMA_BF16(acc[1][2 * ntp],     (uint32_t*)&f1, b0r, b1r);
            MMA_BF16(acc[1][2 * ntp + 1], (uint32_t*)&f1, b2r, b3r);
        }
    }
#pragma unroll
    for (int mi = 0; mi < 2; ++mi) {
        const int rm = wm * 32 + mi * 16 + mrow;
        const float bm  = b1[rm];
        const float bm8 = b1[rm + 8];
#pragma unroll
        for (int nt = 0; nt < 8; ++nt) {
            int col = wn * 64 + nt * 8 + (lane & 3) * 2;
            *(__nv_bfloat162*)&sH1[rm * 136 + col] = __floats2bfloat162_rn(
                fmaxf(acc[mi][nt][0] + bm, 0.f), fmaxf(acc[mi][nt][1] + bm, 0.f));
            *(__nv_bfloat162*)&sH1[(rm + 8) * 136 + col] = __floats2bfloat162_rn(
                fmaxf(acc[mi][nt][2] + bm8, 0.f), fmaxf(acc[mi][nt][3] + bm8, 0.f));
        }
    }
    __syncthreads();

    // ---- gemm2: h2 = relu(W2 @ h1 + b2), K=128 ----
#pragma unroll
    for (int mi = 0; mi < 2; ++mi)
#pragma unroll
        for (int nt = 0; nt < 8; ++nt)
#pragma unroll
            for (int i = 0; i < 4; ++i) acc[mi][nt][i] = 0.f;

#pragma unroll
    for (int ks = 0; ks < 8; ++ks) {
        uint4 f0 = g_w2f[((wm * 2 + 0) * 8 + ks) * 32 + lane];
        uint4 f1 = g_w2f[((wm * 2 + 1) * 8 + ks) * 32 + lane];
#pragma unroll
        for (int ntp = 0; ntp < 4; ++ntp) {
            uint32_t addr = smem_u32(&sH1[(ks * 16 + brow) * 136 + wn * 64 + ntp * 16 + bch]);
            uint32_t b0r, b1r, b2r, b3r;
            LDMX4T(b0r, b1r, b2r, b3r, addr);
            MMA_BF16(acc[0][2 * ntp],     (uint32_t*)&f0, b0r, b1r);
            MMA_BF16(acc[0][2 * ntp + 1], (uint32_t*)&f0, b2r, b3r);
            MMA_BF16(acc[1][2 * ntp],     (uint32_t*)&f1, b0r, b1r);
            MMA_BF16(acc[1][2 * ntp + 1], (uint32_t*)&f1, b2r, b3r);
        }
    }
#pragma unroll
    for (int mi = 0; mi < 2; ++mi) {
        const int rm = wm * 32 + mi * 16 + mrow;
        const float bm  = b2[rm];
        const float bm8 = b2[rm + 8];
#pragma unroll
        for (int nt = 0; nt < 8; ++nt) {
            int col = wn * 64 + nt * 8 + (lane & 3) * 2;
            *(__nv_bfloat162*)&sH2[rm * 136 + col] = __floats2bfloat162_rn(
                fmaxf(acc[mi][nt][0] + bm, 0.f), fmaxf(acc[mi][nt][1] + bm, 0.f));
            *(__nv_bfloat162*)&sH2[(rm + 8) * 136 + col] = __floats2bfloat162_rn(
                fmaxf(acc[mi][nt][2] + bm8, 0.f), fmaxf(acc[mi][nt][3] + bm8, 0.f));
        }
    }
    __syncthreads();

    // ---- gemm3: delta = W3 @ h2 (all 8 warps; warp w -> cols w*16..+15) ----
    {
        const int w3m = lane >> 2;
        float acc3[2][4];
#pragma unroll
        for (int nt = 0; nt < 2; ++nt)
#pragma unroll
            for (int i = 0; i < 4; ++i) acc3[nt][i] = 0.f;

#pragma unroll
        for (int ks = 0; ks < 8; ++ks) {
            uint4 f0 = g_w3f[ks * 32 + lane];
            uint32_t addr = smem_u32(&sH2[(ks * 16 + brow) * 136 + warp * 16 + bch]);
            uint32_t b0r, b1r, b2r, b3r;
            LDMX4T(b0r, b1r, b2r, b3r, addr);
            MMA_BF16(acc3[0], (uint32_t*)&f0, b0r, b1r);
            MMA_BF16(acc3[1], (uint32_t*)&f0, b2r, b3r);
        }
#pragma unroll
        for (int nt = 0; nt < 2; ++nt) {
            int col = warp * 16 + nt * 8 + (lane & 3) * 2;
            sD[w3m * 132 + col]     = acc3[nt][0];
            sD[w3m * 132 + col + 1] = acc3[nt][1];
            if (w3m + 8 < 12) {
                sD[(w3m + 8) * 132 + col]     = acc3[nt][2];
                sD[(w3m + 8) * 132 + col + 1] = acc3[nt][3];
            }
        }
    }
    __syncthreads();

    // ---- NCA epilogue: 128 voxels x 16 ch, 8 channels per thread ----
    {
        const int v   = tid & 127;
        const int grp = tid >> 7;          // 0: ch0-7, 1: ch8-15
        const int s   = (z << 12) + (y0 << 6) + v;

        const float* st = state + (size_t)b * NCH * SPAT;
        float* ot = out + (size_t)b * NCH * SPAT;

        if (grp == 0) {
            float e    = st[s];
            float anch = st[SPAT + s];
            float pos = (z >= 3) ? 1.f : anch;
            float legal = fminf(fmaxf((1.f - e) * pos, 0.f), 1.f);

            ot[0 * SPAT + s] = e;
            ot[1 * SPAT + s] = anch;
            ot[2 * SPAT + s] = st[2 * SPAT + s];
            ot[3 * SPAT + s] = st[3 * SPAT + s];
#pragma unroll
            for (int j = 0; j < 4; ++j) {
                float d = sD[j * 132 + v] + b3[j];
                float g = fminf(fmaxf(st[(4 + j) * SPAT + s] + 0.1f * d, 0.f), 1.f);
                if (j == 0) g = g * (1.f - e) * legal;
                ot[(4 + j) * SPAT + s] = g;
            }
        } else {
#pragma unroll
            for (int j = 4; j < 12; ++j) {
                float d = sD[j * 132 + v] + b3[j];
                float g = fminf(fmaxf(st[(4 + j) * SPAT + s] + 0.1f * d, 0.f), 1.f);
                ot[(4 + j) * SPAT + s] = g;
            }
        }
    }
}

// ---------------------------------------------------------------------------
extern "C" void kernel_launch(void* const* d_in, const int* in_sizes, int n_in,
                              void* d_out, int out_size) {
    const float* state = (const float*)d_in[0];
    const float* w1 = (const float*)d_in[1];
    const float* b1 = (const float*)d_in[2];
    const float* w2 = (const float*)d_in[3];
    const float* b2 = (const float*)d_in[4];
    const float* w3 = (const float*)d_in[5];
    const float* b3 = (const float*)d_in[6];
    float* out = (float*)d_out;

    cudaFuncSetAttribute(k_fused, cudaFuncAttributeMaxDynamicSharedMemorySize,
                         SMEM_BYTES);

    // 1) weights fp32 -> bf16 in fragment order
    k_convert<<<24, 256>>>(w1, w2, w3);

    // 2) fused perceive + MLP + epilogue (one block per 128 voxels)
    k_fused<<<NTOT / 128, 256, SMEM_BYTES>>>(state, b1, b2, b3, out);
}